// round 1
// baseline (speedup 1.0000x reference)
#include <cuda_runtime.h>
#include <cstdint>

// ----------------------------------------------------------------------------
// ProposalLayer (RPN): decode anchors -> top-6000 (stable) -> greedy NMS -> 300
// H=128, W=192, A=9, STRIDE=16, PRE_NMS=6000, POST_NMS=300, THRESH=0.7
// ----------------------------------------------------------------------------

#define HH 128
#define WW 192
#define HWSZ (HH * WW)          // 24576
#define NA 9
#define NTOT (NA * HWSZ)        // 221184
#define PRE_NMS 6000
#define POST_NMS 300
#define SEL_CAP 8192
#define COLB 94                 // ceil(6000/64)

// Anchor widths/heights (x2-x1+1); all anchor centers are at (8,8) + 16*(w,h).
__constant__ float c_aw[NA] = {184.f, 368.f, 736.f, 128.f, 256.f, 512.f, 88.f, 176.f, 352.f};
__constant__ float c_ah[NA] = {96.f, 192.f, 384.f, 128.f, 256.f, 512.f, 176.f, 352.f, 704.f};

// ------------------------------- device state -------------------------------
__device__ float4 g_boxes[NTOT];                 // decoded boxes
__device__ unsigned int g_scf[NTOT];             // order-preserving score keys
__device__ unsigned long long g_sel[SEL_CAP];    // selected (then sorted) keys
__device__ int g_selcnt;
__device__ unsigned int g_hist[4][256];
struct SelState { unsigned int prefix; int krem; int done; unsigned int thresh; };
__device__ SelState g_state;
__device__ float4 g_tboxes[SEL_CAP];             // top-6000 boxes, sorted order
__device__ int g_tvalid[SEL_CAP];
__device__ unsigned long long g_mask[(size_t)PRE_NMS * COLB];  // suppression bits (j > i)

// ------------------------------- kernels ------------------------------------

__global__ void reset_kernel() {
    int t = threadIdx.x;
    for (int i = t; i < 4 * 256; i += blockDim.x)
        ((unsigned int*)g_hist)[i] = 0u;
    if (t == 0) {
        g_state.prefix = 0u;
        g_state.krem = PRE_NMS;
        g_state.done = 0;
        g_state.thresh = 0u;
        g_selcnt = 0;
    }
}

__global__ void decode_kernel(const float* __restrict__ scores,
                              const float* __restrict__ deltas,
                              const float* __restrict__ iminfo) {
    int t = blockIdx.x * blockDim.x + threadIdx.x;
    if (t >= NTOT) return;
    int a = t / HWSZ;
    int pix = t - a * HWSZ;
    int wi = pix % WW;
    int hi = pix / WW;

    float sc = scores[(NA + a) * HWSZ + pix];
    float dx = deltas[(4 * a + 0) * HWSZ + pix];
    float dy = deltas[(4 * a + 1) * HWSZ + pix];
    float dw = deltas[(4 * a + 2) * HWSZ + pix];
    float dh = deltas[(4 * a + 3) * HWSZ + pix];
    dw = fminf(fmaxf(dw, -10.f), 10.f);
    dh = fminf(fmaxf(dh, -10.f), 10.f);

    float AW = c_aw[a], AH = c_ah[a];
    float cx = dx * AW + (8.f + 16.f * (float)wi);
    float cy = dy * AH + (8.f + 16.f * (float)hi);
    float pw = expf(dw) * AW;
    float ph = expf(dh) * AH;
    float x1 = cx - 0.5f * pw, x2 = cx + 0.5f * pw;
    float y1 = cy - 0.5f * ph, y2 = cy + 0.5f * ph;

    float maxx = iminfo[1] - 1.0f;
    float maxy = iminfo[0] - 1.0f;
    x1 = fminf(fmaxf(x1, 0.f), maxx);
    x2 = fminf(fmaxf(x2, 0.f), maxx);
    y1 = fminf(fmaxf(y1, 0.f), maxy);
    y2 = fminf(fmaxf(y2, 0.f), maxy);

    float minsz = 16.f * iminfo[2];
    bool valid = (x2 - x1 + 1.0f >= minsz) && (y2 - y1 + 1.0f >= minsz);

    int i = pix * NA + a;  // reference flat ordering: ((h*W+w)*A + a)
    g_boxes[i] = make_float4(x1, y1, x2, y2);

    unsigned int u;
    if (valid) {
        u = __float_as_uint(sc);
        u = (u & 0x80000000u) ? ~u : (u | 0x80000000u);
    } else {
        u = 0x007FFFFFu;  // flip(-inf)
    }
    g_scf[i] = u;
}

__global__ void hist_kernel(int p) {
    if (g_state.done) return;
    __shared__ unsigned int sh[256];
    int tid = threadIdx.x;
    sh[tid] = 0u;
    __syncthreads();
    int i = blockIdx.x * blockDim.x + tid;
    int shift = 24 - 8 * p;
    unsigned int prefix = g_state.prefix;
    if (i < NTOT) {
        unsigned int v = g_scf[i];
        bool match = (p == 0) || ((v >> (shift + 8)) == prefix);
        if (match) atomicAdd(&sh[(v >> shift) & 0xFFu], 1u);
    }
    __syncthreads();
    if (sh[tid]) atomicAdd(&g_hist[p][tid], sh[tid]);
}

__global__ void pick_kernel(int p) {
    __shared__ unsigned int h[256];
    int tid = threadIdx.x;
    if (g_state.done) return;
    for (int i = tid; i < 256; i += blockDim.x) h[i] = g_hist[p][i];
    __syncthreads();
    if (tid != 0) return;
    int krem = g_state.krem;
    unsigned int c = 0, hb = 0;
    int b = 0;
    for (int bb = 255; bb >= 0; bb--) {
        unsigned int hh = h[bb];
        if (c + hh >= (unsigned int)krem) { b = bb; hb = hh; break; }
        c += hh;
    }
    int shift = 24 - 8 * p;
    unsigned int total_ge = (unsigned int)(PRE_NMS - krem) + c + hb;
    unsigned int newprefix = (g_state.prefix << 8) | (unsigned int)b;
    if (total_ge <= SEL_CAP || p == 3) {
        g_state.done = 1;
        g_state.thresh = newprefix << shift;
    } else {
        g_state.prefix = newprefix;
        g_state.krem = krem - (int)c;
    }
}

__global__ void compact_kernel() {
    int i = blockIdx.x * blockDim.x + threadIdx.x;
    if (i >= NTOT) return;
    unsigned int v = g_scf[i];
    if (v >= g_state.thresh) {
        int p = atomicAdd(&g_selcnt, 1);
        if (p < SEL_CAP)
            g_sel[p] = ((unsigned long long)v << 32) | (unsigned int)(~(unsigned int)i);
    }
}

// One-block bitonic sort of 8192 u64 keys (descending). 64KB dynamic smem.
__global__ void sort_kernel() {
    extern __shared__ unsigned long long s[];
    int tid = threadIdx.x;
    int cnt = g_selcnt;
    if (cnt > SEL_CAP) cnt = SEL_CAP;
    for (int i = tid; i < SEL_CAP; i += 1024)
        s[i] = (i < cnt) ? g_sel[i] : 0ull;
    __syncthreads();
    for (int k = 2; k <= SEL_CAP; k <<= 1) {
        for (int j = k >> 1; j > 0; j >>= 1) {
            for (int t = tid; t < SEL_CAP; t += 1024) {
                int ixj = t ^ j;
                if (ixj > t) {
                    unsigned long long a = s[t], b = s[ixj];
                    bool sw = ((t & k) == 0) ? (a < b) : (a > b);
                    if (sw) { s[t] = b; s[ixj] = a; }
                }
            }
            __syncthreads();
        }
    }
    for (int i = tid; i < SEL_CAP; i += 1024) g_sel[i] = s[i];
}

__global__ void gather_kernel() {
    int j = blockIdx.x * blockDim.x + threadIdx.x;
    if (j >= PRE_NMS) return;
    unsigned long long key = g_sel[j];
    unsigned int idx = ~(unsigned int)(key & 0xFFFFFFFFull);
    g_tboxes[j] = g_boxes[idx];
    g_tvalid[j] = ((unsigned int)(key >> 32)) >= 0x80000000u ? 1 : 0;
}

// Suppression mask: for each row i, bit b of word cb says box j=cb*64+b (j>i)
// has IoU(i,j) > 0.7. Upper-triangular blocks only; rest stays zero.
__global__ void nms_mask_kernel() {
    int rb = blockIdx.x, cb = blockIdx.y;
    if (cb < rb) return;
    __shared__ float4 cbox[64];
    int t = threadIdx.x;
    int j0 = cb * 64;
    cbox[t] = (j0 + t < PRE_NMS) ? g_tboxes[j0 + t] : make_float4(0.f, 0.f, 0.f, 0.f);
    __syncthreads();
    int i = rb * 64 + t;
    if (i >= PRE_NMS) return;
    float4 bi = g_tboxes[i];
    float ai = (bi.z - bi.x) * (bi.w - bi.y);
    unsigned long long bits = 0ull;
    int jmax = min(64, PRE_NMS - j0);
    #pragma unroll 4
    for (int b = 0; b < jmax; b++) {
        int j = j0 + b;
        if (j <= i) continue;
        float4 bj = cbox[b];
        float xx1 = fmaxf(bi.x, bj.x), yy1 = fmaxf(bi.y, bj.y);
        float xx2 = fminf(bi.z, bj.z), yy2 = fminf(bi.w, bj.w);
        float w = fmaxf(xx2 - xx1, 0.f);
        float h = fmaxf(yy2 - yy1, 0.f);
        float inter = w * h;
        float aj = (bj.z - bj.x) * (bj.w - bj.y);
        float iou = inter / (ai + aj - inter);
        if (iou > 0.7f) bits |= (1ull << b);
    }
    g_mask[(size_t)i * COLB + cb] = bits;
}

// Sequential greedy scan, single warp. remv vector (94 u64) lives in registers
// (3 per lane). Early-exit at 300 kept (only first 300 of stable order matter).
__global__ void nms_scan_kernel(float* __restrict__ out) {
    int lane = threadIdx.x;
    for (int t = lane; t < POST_NMS * 5; t += 32) out[t] = 0.0f;
    __shared__ unsigned char sval[PRE_NMS];
    for (int t = lane; t < PRE_NMS; t += 32) sval[t] = (unsigned char)g_tvalid[t];
    __syncwarp();

    unsigned long long r0 = 0ull, r1 = 0ull, r2 = 0ull;
    int kept = 0;
    for (int i = 0; i < PRE_NMS; i++) {
        int w = i >> 6, bit = i & 63;
        unsigned long long rv = (w < 32) ? r0 : ((w < 64) ? r1 : r2);
        unsigned long long word = __shfl_sync(0xFFFFFFFFu, rv, w & 31);
        bool suppressed = (word >> bit) & 1ull;
        if (!suppressed && sval[i]) {
            if (lane < 5) {
                float4 b = g_tboxes[i];
                float v = (lane == 0) ? 0.f :
                          (lane == 1) ? b.x :
                          (lane == 2) ? b.y :
                          (lane == 3) ? b.z : b.w;
                out[kept * 5 + lane] = v;
            }
            kept++;
            if (kept >= POST_NMS) break;
            const unsigned long long* row = &g_mask[(size_t)i * COLB];
            r0 |= row[lane];
            if (lane + 32 < COLB) r1 |= row[lane + 32];
            if (lane + 64 < COLB) r2 |= row[lane + 64];
        }
    }
}

// ------------------------------- launch -------------------------------------
extern "C" void kernel_launch(void* const* d_in, const int* in_sizes, int n_in,
                              void* d_out, int out_size) {
    const float* scores = (const float*)d_in[0];
    const float* deltas = (const float*)d_in[1];
    const float* iminfo = (const float*)d_in[2];
    float* out = (float*)d_out;

    cudaFuncSetAttribute(sort_kernel, cudaFuncAttributeMaxDynamicSharedMemorySize, 65536);

    reset_kernel<<<1, 256>>>();
    decode_kernel<<<(NTOT + 255) / 256, 256>>>(scores, deltas, iminfo);
    for (int p = 0; p < 4; p++) {
        hist_kernel<<<(NTOT + 255) / 256, 256>>>(p);
        pick_kernel<<<1, 256>>>(p);
    }
    compact_kernel<<<(NTOT + 255) / 256, 256>>>();
    sort_kernel<<<1, 1024, 65536>>>();
    gather_kernel<<<(PRE_NMS + 255) / 256, 256>>>();
    dim3 mg(COLB, COLB);
    nms_mask_kernel<<<mg, 64>>>();
    nms_scan_kernel<<<1, 32>>>(out);
}